// round 6
// baseline (speedup 1.0000x reference)
#include <cuda_runtime.h>
#include <cuda_bf16.h>
#include <cstdint>
#include <cstddef>

#define NB   8192
#define NBAT 4
#define XS_W 136   // conv1 smem row width (halo 3+5, padded)

// ---------------- scratch (device globals) ----------------------------------
__device__ __align__(16) float g_wemb_t[56 * 7 * 56];       // [a_in][k][a_out]
__device__ __align__(16) float g_wk_t[128 * 128];           // [e][o]
// conv2 weights: [tap][eo][ei] bf16, split hi/lo
__device__ __align__(16) __nv_bfloat16 g_wat_hi[7 * 128 * 128];
__device__ __align__(16) __nv_bfloat16 g_wat_lo[7 * 128 * 128];
// conv1 output, split bf16: [b][a(56)][ei(128)]
__device__ __align__(16) __nv_bfloat16 g_h1_hi[(size_t)NB * 56 * 128];
__device__ __align__(16) __nv_bfloat16 g_h1_lo[(size_t)NB * 56 * 128];
__device__ __align__(16) float g_q[NB * 128];               // q pre-LN

// ---------------- helpers ----------------------------------------------------
__device__ __forceinline__ void fma2(unsigned long long &d,
                                     unsigned long long a,
                                     unsigned long long b) {
    asm("fma.rn.f32x2 %0, %1, %2, %3;" : "=l"(d) : "l"(a), "l"(b), "l"(d));
}
__device__ __forceinline__ unsigned long long bc2(float x) {
    unsigned int xi = __float_as_uint(x);
    unsigned long long r;
    asm("mov.b64 %0, {%1, %2};" : "=l"(r) : "r"(xi), "r"(xi));
    return r;
}
__device__ __forceinline__ float2 unpk(unsigned long long v) {
    unsigned int lo, hi;
    asm("mov.b64 {%0, %1}, %2;" : "=r"(lo), "=r"(hi) : "l"(v));
    float2 f; f.x = __uint_as_float(lo); f.y = __uint_as_float(hi);
    return f;
}
__device__ __forceinline__ float silu_f(float v) {
    float e = __expf(-v);
    float r;
    asm("rcp.approx.f32 %0, %1;" : "=f"(r) : "f"(1.0f + e));
    return v * r;
}
__device__ __forceinline__ uint32_t smem_u32(const void* p) {
    uint32_t a;
    asm("{ .reg .u64 t; cvta.to.shared.u64 t, %1; cvt.u32.u64 %0, t; }"
        : "=r"(a) : "l"(p));
    return a;
}
__device__ __forceinline__ void ldsm4(uint32_t &r0, uint32_t &r1,
                                      uint32_t &r2, uint32_t &r3, uint32_t addr) {
    asm volatile("ldmatrix.sync.aligned.m8n8.x4.shared.b16 {%0,%1,%2,%3}, [%4];"
        : "=r"(r0), "=r"(r1), "=r"(r2), "=r"(r3) : "r"(addr));
}
__device__ __forceinline__ void ldsm2(uint32_t &r0, uint32_t &r1, uint32_t addr) {
    asm volatile("ldmatrix.sync.aligned.m8n8.x2.shared.b16 {%0,%1}, [%2];"
        : "=r"(r0), "=r"(r1) : "r"(addr));
}
__device__ __forceinline__ void mma_bf16(float* d,
                                         uint32_t a0, uint32_t a1, uint32_t a2, uint32_t a3,
                                         uint32_t b0, uint32_t b1) {
    asm volatile("mma.sync.aligned.m16n8k16.row.col.f32.bf16.bf16.f32 "
                 "{%0,%1,%2,%3}, {%4,%5,%6,%7}, {%8,%9}, {%0,%1,%2,%3};"
                 : "+f"(d[0]), "+f"(d[1]), "+f"(d[2]), "+f"(d[3])
                 : "r"(a0), "r"(a1), "r"(a2), "r"(a3), "r"(b0), "r"(b1));
}

// ---------------- K0: repack weights ----------------------------------------
__global__ void repack_kernel(const float* __restrict__ w_emb,
                              const float* __restrict__ w_atlas,
                              const float* __restrict__ w_k) {
    int i = blockIdx.x * 256 + threadIdx.x;
    if (i < 56 * 56 * 7) {
        int ao = i / 392, r = i % 392, ai = r / 7, k = r % 7;
        g_wemb_t[(ai * 7 + k) * 56 + ao] = w_emb[i];
    }
    if (i < 128 * 128 * 7) {
        float v = w_atlas[i];
        int eo = i / 896, r = i % 896, ei = r / 7, k = r % 7;
        __nv_bfloat16 hi = __float2bfloat16(v);
        __nv_bfloat16 lo = __float2bfloat16(v - __bfloat162float(hi));
        g_wat_hi[k * 16384 + eo * 128 + ei] = hi;
        g_wat_lo[k * 16384 + eo * 128 + ei] = lo;
    }
    if (i < 128 * 128) {
        int o = i / 128, e = i % 128;
        g_wk_t[e * 128 + o] = w_k[i];
    }
}

// ---------------- K1: conv1 over E + SiLU -> h1 [b][a][e] bf16 hi/lo ---------
__global__ void __launch_bounds__(128, 5)
conv1_kernel(const float* __restrict__ x, const float* __restrict__ b_emb) {
    __shared__ __align__(16) float xs[56 * XS_W];
    int t = threadIdx.x;
    int b = blockIdx.x;

    const float* xb = x + (size_t)b * 56 * 128;
    for (int i = t; i < 56 * 128; i += 128) {
        int a = i >> 7, e = i & 127;
        xs[a * XS_W + 3 + e] = xb[i];
    }
    if (t < 56) {
        float* row = xs + t * XS_W;
        row[0] = 0.f; row[1] = 0.f; row[2] = 0.f;
        row[131] = 0.f; row[132] = 0.f; row[133] = 0.f; row[134] = 0.f; row[135] = 0.f;
    }
    __syncthreads();

    int ep = t & 63, ah = t >> 6;
    int e0 = 2 * ep, aoff = 28 * ah;

    unsigned long long acc0[14], acc1[14];
#pragma unroll
    for (int j = 0; j < 14; j++) { acc0[j] = 0ULL; acc1[j] = 0ULL; }

    for (int ai = 0; ai < 56; ai++) {
        const float* xr = xs + ai * XS_W + e0;
        float xv[8];
#pragma unroll
        for (int j = 0; j < 8; j++) xv[j] = xr[j];
#pragma unroll
        for (int k = 0; k < 7; k++) {
            unsigned long long xb0 = bc2(xv[k]);
            unsigned long long xb1 = bc2(xv[k + 1]);
            const ulonglong2* wr = reinterpret_cast<const ulonglong2*>(
                g_wemb_t + (ai * 7 + k) * 56 + aoff);
#pragma unroll
            for (int p = 0; p < 7; p++) {
                ulonglong2 w = wr[p];
                fma2(acc0[2 * p],     w.x, xb0);
                fma2(acc0[2 * p + 1], w.y, xb0);
                fma2(acc1[2 * p],     w.x, xb1);
                fma2(acc1[2 * p + 1], w.y, xb1);
            }
        }
    }
    __syncthreads();   // done reading xs; reuse as bf16 staging [a][64 e-pairs]

    __nv_bfloat162* so = reinterpret_cast<__nv_bfloat162*>(xs);

    // pass 1: hi
#pragma unroll
    for (int j = 0; j < 14; j++) {
        int a = aoff + 2 * j;
        float2 f0 = unpk(acc0[j]);   // out[a][e0], out[a+1][e0]
        float2 f1 = unpk(acc1[j]);   // out[a][e0+1], out[a+1][e0+1]
        float be0 = b_emb[a], be1 = b_emb[a + 1];
        float v00 = silu_f(f0.x + be0), v01 = silu_f(f1.x + be0);
        float v10 = silu_f(f0.y + be1), v11 = silu_f(f1.y + be1);
        __nv_bfloat162 p0, p1;
        p0.x = __float2bfloat16(v00); p0.y = __float2bfloat16(v01);
        p1.x = __float2bfloat16(v10); p1.y = __float2bfloat16(v11);
        so[a * 64 + ep]       = p0;
        so[(a + 1) * 64 + ep] = p1;
    }
    __syncthreads();
    {
        const uint4* s4 = reinterpret_cast<const uint4*>(xs);
        uint4* d4 = reinterpret_cast<uint4*>(g_h1_hi + (size_t)b * 7168);
        for (int i = t; i < 896; i += 128) d4[i] = s4[i];
    }
    __syncthreads();

    // pass 2: lo (recompute from live accs)
#pragma unroll
    for (int j = 0; j < 14; j++) {
        int a = aoff + 2 * j;
        float2 f0 = unpk(acc0[j]);
        float2 f1 = unpk(acc1[j]);
        float be0 = b_emb[a], be1 = b_emb[a + 1];
        float v00 = silu_f(f0.x + be0), v01 = silu_f(f1.x + be0);
        float v10 = silu_f(f0.y + be1), v11 = silu_f(f1.y + be1);
        __nv_bfloat162 p0, p1;
        p0.x = __float2bfloat16(v00 - __bfloat162float(__float2bfloat16(v00)));
        p0.y = __float2bfloat16(v01 - __bfloat162float(__float2bfloat16(v01)));
        p1.x = __float2bfloat16(v10 - __bfloat162float(__float2bfloat16(v10)));
        p1.y = __float2bfloat16(v11 - __bfloat162float(__float2bfloat16(v11)));
        so[a * 64 + ep]       = p0;
        so[(a + 1) * 64 + ep] = p1;
    }
    __syncthreads();
    {
        const uint4* s4 = reinterpret_cast<const uint4*>(xs);
        uint4* d4 = reinterpret_cast<uint4*>(g_h1_lo + (size_t)b * 7168);
        for (int i = t; i < 896; i += 128) d4[i] = s4[i];
    }
}

// ---------------- K2: conv2 via mma.sync bf16 (split hi/lo) ------------------
// 4 batches per 256-thread CTA (8 warps). Warp wid owns eo rows [16wid,16wid+16).
// smem: Hs[bi][split][64 rows][128 ei] bf16 (halo rows zero), Ws[split][128][128].
__global__ void __launch_bounds__(256, 1)
conv2_kernel(const float* __restrict__ b_atlas) {
    extern __shared__ __align__(16) unsigned char cs[];
    unsigned char* Hs = cs;               // 4 * 2 * 16384 = 131072 B
    unsigned char* Ws = cs + 131072;      // 2 * 32768 = 65536 B

    int tid = threadIdx.x, lane = tid & 31, wid = tid >> 5;
    int b0 = blockIdx.x * NBAT;

    // load H tiles (rows 3..58 = a 0..55; halo rows zero)
    {
        uint4* d = reinterpret_cast<uint4*>(Hs);
        const uint4* shi = reinterpret_cast<const uint4*>(g_h1_hi);
        const uint4* slo = reinterpret_cast<const uint4*>(g_h1_lo);
        for (int i = tid; i < NBAT * 2 * 1024; i += 256) {
            int slot = i & 1023;
            int sp = (i >> 10) & 1;
            int bi = i >> 11;
            int row = slot >> 4, c = slot & 15;
            uint4 v = make_uint4(0, 0, 0, 0);
            int a = row - 3;
            if (a >= 0 && a < 56) {
                size_t s = ((size_t)(b0 + bi) * 56 + a) * 16 + c;
                v = sp ? slo[s] : shi[s];
            }
            d[i] = v;
        }
    }

    float acc[NBAT][7][4];
#pragma unroll
    for (int bi = 0; bi < NBAT; bi++)
#pragma unroll
        for (int nt = 0; nt < 7; nt++)
#pragma unroll
            for (int j = 0; j < 4; j++) acc[bi][nt][j] = 0.f;

    uint32_t sHs = smem_u32(Hs);
    uint32_t sWs = smem_u32(Ws);
    uint32_t aBase = sWs + (wid * 16 + (lane & 15)) * 256 + ((lane >> 4) * 16);
    uint32_t bRowSel = (lane & 7);
    uint32_t bColSel = ((lane >> 3) & 1) * 16;

    for (int tap = 0; tap < 7; tap++) {
        __syncthreads();
        {
            const uint4* whi = reinterpret_cast<const uint4*>(g_wat_hi + tap * 16384);
            const uint4* wlo = reinterpret_cast<const uint4*>(g_wat_lo + tap * 16384);
            uint4* dw = reinterpret_cast<uint4*>(Ws);
            for (int i = tid; i < 2048; i += 256) {
                dw[i] = whi[i];
                dw[i + 2048] = wlo[i];
            }
        }
        __syncthreads();

#pragma unroll
        for (int kf = 0; kf < 8; kf++) {
            uint32_t aAddr = aBase + kf * 32;
            uint32_t ah0, ah1, ah2, ah3, al0, al1, al2, al3;
            ldsm4(ah0, ah1, ah2, ah3, aAddr);
            ldsm4(al0, al1, al2, al3, aAddr + 32768);
#pragma unroll
            for (int bi = 0; bi < NBAT; bi++) {
                uint32_t hBase = sHs + bi * 32768;
#pragma unroll
                for (int nt = 0; nt < 7; nt++) {
                    uint32_t row = nt * 8 + bRowSel + tap;     // <= 61 < 64
                    uint32_t bAddr = hBase + row * 256 + kf * 32 + bColSel;
                    uint32_t bh0, bh1, bl0, bl1;
                    ldsm2(bh0, bh1, bAddr);
                    ldsm2(bl0, bl1, bAddr + 16384);
                    mma_bf16(acc[bi][nt], ah0, ah1, ah2, ah3, bh0, bh1);
                    mma_bf16(acc[bi][nt], ah0, ah1, ah2, ah3, bl0, bl1);
                    mma_bf16(acc[bi][nt], al0, al1, al2, al3, bh0, bh1);
                }
            }
        }
    }

    // epilogue: silu + mean over a, reduce across 4-lane groups
    int r0 = lane >> 2;
#pragma unroll
    for (int bi = 0; bi < NBAT; bi++) {
#pragma unroll
        for (int half = 0; half < 2; half++) {
            int eo = wid * 16 + r0 + 8 * half;
            float bias = b_atlas[eo];
            float s = 0.f;
#pragma unroll
            for (int nt = 0; nt < 7; nt++) {
                s += silu_f(acc[bi][nt][2 * half]     + bias);
                s += silu_f(acc[bi][nt][2 * half + 1] + bias);
            }
            s += __shfl_xor_sync(0xFFFFFFFF, s, 1);
            s += __shfl_xor_sync(0xFFFFFFFF, s, 2);
            if ((lane & 3) == 0)
                g_q[(size_t)(b0 + bi) * 128 + eo] = s * (1.0f / 56.0f);
        }
    }
}

// ---------------- K3: k-proj + LN + attention + diff-softmax -----------------
// 1 batch per 128-thread CTA. ks transposed [o][l], pitch 57 (conflict-free).
__global__ void __launch_bounds__(128, 3)
attn_kernel(const float* __restrict__ x,
            const float* __restrict__ qn_w, const float* __restrict__ qn_b,
            const float* __restrict__ kn_w, const float* __restrict__ kn_b,
            const float* __restrict__ lq1, const float* __restrict__ lk1,
            const float* __restrict__ lq2, const float* __restrict__ lk2,
            float* __restrict__ out) {
    extern __shared__ __align__(16) float sm[];
    int t = threadIdx.x;
    int b = blockIdx.x;

    float* xsT = sm;            // [e][l] (128*56)
    float* ks  = sm + 7168;     // [o][l] pitch 57 (128*57)
    float* qv  = sm + 14464;    // 128
    float* sc  = sm + 14592;    // [h2][l] 8*56
    float* dd  = sm + 15040;    // [hp][l] 4*56
    float* lam = sm + 15264;

    const float* xb = x + (size_t)b * 7168;
    for (int i = t; i < 7168; i += 128) {
        int l = i >> 7, e = i & 127;
        xsT[e * 56 + l] = xb[i];
    }
    qv[t] = g_q[b * 128 + t];
    if (t == 0) {
        float s1 = 0.f, s2 = 0.f;
#pragma unroll
        for (int d = 0; d < 16; d++) { s1 += lq1[d] * lk1[d]; s2 += lq2[d] * lk2[d]; }
        lam[0] = __expf(s1) - __expf(s2) + 0.7f;
    }
    __syncthreads();

    // k projection: thread t owns column o=t; f32x2 lanes = l pairs
    unsigned long long acc[28];
#pragma unroll
    for (int p = 0; p < 28; p++) acc[p] = 0ULL;
    for (int e = 0; e < 128; e++) {
        unsigned long long wb = bc2(g_wk_t[e * 128 + t]);
        const ulonglong2* xr = reinterpret_cast<const ulonglong2*>(xsT + e * 56);
#pragma unroll
        for (int p = 0; p < 14; p++) {
            ulonglong2 xq = xr[p];
            fma2(acc[2 * p],     xq.x, wb);
            fma2(acc[2 * p + 1], xq.y, wb);
        }
    }
    {
        float* kr = ks + t * 57;
#pragma unroll
        for (int j = 0; j < 28; j++) {
            float2 f = unpk(acc[j]);
            kr[2 * j]     = f.x;
            kr[2 * j + 1] = f.y;
        }
    }
    __syncthreads();

    // LayerNorm k: group (l, h) over 16 o-rows
    for (int gI = t; gI < 448; gI += 128) {
        int h = gI / 56, l = gI - h * 56;
        int ob = h * 16;
        float m = 0.f;
#pragma unroll
        for (int d = 0; d < 16; d++) m += ks[(ob + d) * 57 + l];
        m *= (1.0f / 16.0f);
        float var = 0.f;
#pragma unroll
        for (int d = 0; d < 16; d++) {
            float dv = ks[(ob + d) * 57 + l] - m;
            var += dv * dv;
        }
        var *= (1.0f / 16.0f);
        float rs = rsqrtf(var + 1e-5f);
#pragma unroll
        for (int d = 0; d < 16; d++) {
            float* p = ks + (ob + d) * 57 + l;
            *p = (*p - m) * rs * kn_w[d] + kn_b[d];
        }
    }
    if (t < 8) {
        float* qp = qv + t * 16;
        float m = 0.f;
#pragma unroll
        for (int d = 0; d < 16; d++) m += qp[d];
        m *= (1.0f / 16.0f);
        float var = 0.f;
#pragma unroll
        for (int d = 0; d < 16; d++) { float dv = qp[d] - m; var += dv * dv; }
        var *= (1.0f / 16.0f);
        float rs = rsqrtf(var + 1e-5f);
#pragma unroll
        for (int d = 0; d < 16; d++)
            qp[d] = ((qp[d] - m) * rs * qn_w[d] + qn_b[d]) * 0.25f;  // * HD^-0.5
    }
    __syncthreads();

    // attention scores
    for (int gI = t; gI < 448; gI += 128) {
        int h = gI / 56, l = gI - h * 56;
        int ob = h * 16;
        const float* qp = qv + h * 16;
        float s = 0.f;
#pragma unroll
        for (int d = 0; d < 16; d++) s += qp[d] * ks[(ob + d) * 57 + l];
        sc[h * 56 + l] = s;
    }
    __syncthreads();

    // softmax per head
    if (t < 8) {
        float* r = sc + t * 56;
        float mx = -1e30f;
        for (int l = 0; l < 56; l++) mx = fmaxf(mx, r[l]);
        float sum = 0.f;
        for (int l = 0; l < 56; l++) { float e = __expf(r[l] - mx); r[l] = e; sum += e; }
        float inv = 1.0f / sum;
        for (int l = 0; l < 56; l++) r[l] *= inv;
    }
    __syncthreads();

    // diff + softmax per head pair
    if (t < 4) {
        float lamv = lam[0];
        const float* p0 = sc + (2 * t) * 56;
        const float* p1 = sc + (2 * t + 1) * 56;
        float* dr = dd + t * 56;
        float mx = -1e30f;
        for (int l = 0; l < 56; l++) {
            float d = p0[l] - lamv * p1[l];
            dr[l] = d;
            mx = fmaxf(mx, d);
        }
        float sum = 0.f;
        for (int l = 0; l < 56; l++) { float e = __expf(dr[l] - mx); dr[l] = e; sum += e; }
        float inv = 1.0f / sum;
        for (int l = 0; l < 56; l++) dr[l] *= inv;
    }
    __syncthreads();

    if (t < 56) {
        out[(size_t)b * 56 + t] =
            0.25f * (dd[t] + dd[56 + t] + dd[112 + t] + dd[168 + t]);
    }
}

// ---------------- launch -----------------------------------------------------
extern "C" void kernel_launch(void* const* d_in, const int* in_sizes, int n_in,
                              void* d_out, int out_size) {
    const float* x       = (const float*)d_in[0];
    const float* w_emb   = (const float*)d_in[1];
    const float* b_emb   = (const float*)d_in[2];
    const float* w_atlas = (const float*)d_in[3];
    const float* b_atlas = (const float*)d_in[4];
    const float* w_k     = (const float*)d_in[5];
    const float* qn_w    = (const float*)d_in[6];
    const float* qn_b    = (const float*)d_in[7];
    const float* kn_w    = (const float*)d_in[8];
    const float* kn_b    = (const float*)d_in[9];
    const float* lq1     = (const float*)d_in[10];
    const float* lk1     = (const float*)d_in[11];
    const float* lq2     = (const float*)d_in[12];
    const float* lk2     = (const float*)d_in[13];
    float* out = (float*)d_out;

    const int SMEM2 = 131072 + 65536;               // 196,608 B
    const int SMEM3 = 15268 * (int)sizeof(float);   // 61,072 B
    cudaFuncSetAttribute((const void*)conv2_kernel,
                         cudaFuncAttributeMaxDynamicSharedMemorySize, SMEM2);
    cudaFuncSetAttribute((const void*)attn_kernel,
                         cudaFuncAttributeMaxDynamicSharedMemorySize, SMEM3);

    repack_kernel<<<448, 256>>>(w_emb, w_atlas, w_k);
    conv1_kernel<<<NB, 128>>>(x, b_emb);
    conv2_kernel<<<NB / NBAT, 256, SMEM2>>>(b_atlas);
    attn_kernel<<<NB, 128, SMEM3>>>(x, qn_w, qn_b, kn_w, kn_b,
                                    lq1, lk1, lq2, lk2, out);
    (void)in_sizes; (void)n_in; (void)out_size;
}

// round 11
// speedup vs baseline: 1.2725x; 1.2725x over previous
#include <cuda_runtime.h>
#include <cstdint>
#include <cstddef>

#define NB   8192
#define XS_W 136   // conv1 smem row width (halo 3+5, padded)

// ---------------- scratch (device globals) ----------------------------------
__device__ __align__(16) float g_wemb_t[56 * 7 * 56];       // [a_in][k][a_out]
__device__ __align__(16) float g_watlas_t[128 * 7 * 128];   // [e_in][k][e_out]
__device__ __align__(16) float g_wk_t[128 * 128];           // [e][o]
__device__ __align__(16) float g_h1[(size_t)NB * 128 * 64]; // [b][e][a+3], halo 0
__device__ __align__(16) float g_q[NB * 128];               // q pre-LN

// ---------------- f32x2 helpers ---------------------------------------------
__device__ __forceinline__ void fma2(unsigned long long &d,
                                     unsigned long long a,
                                     unsigned long long b) {
    asm("fma.rn.f32x2 %0, %1, %2, %3;" : "=l"(d) : "l"(a), "l"(b), "l"(d));
}
__device__ __forceinline__ unsigned long long bc2(float x) {
    unsigned int xi = __float_as_uint(x);
    unsigned long long r;
    asm("mov.b64 %0, {%1, %2};" : "=l"(r) : "r"(xi), "r"(xi));
    return r;
}
__device__ __forceinline__ float2 unpk(unsigned long long v) {
    unsigned int lo, hi;
    asm("mov.b64 {%0, %1}, %2;" : "=r"(lo), "=r"(hi) : "l"(v));
    float2 f; f.x = __uint_as_float(lo); f.y = __uint_as_float(hi);
    return f;
}
__device__ __forceinline__ float silu_f(float v) {
    return v / (1.0f + __expf(-v));
}

// ---------------- K0: repack weights ----------------------------------------
__global__ void repack_kernel(const float* __restrict__ w_emb,
                              const float* __restrict__ w_atlas,
                              const float* __restrict__ w_k) {
    int i = blockIdx.x * 256 + threadIdx.x;
    if (i < 56 * 56 * 7) {
        int ao = i / 392, r = i % 392, ai = r / 7, k = r % 7;
        g_wemb_t[(ai * 7 + k) * 56 + ao] = w_emb[i];
    }
    if (i < 128 * 128 * 7) {
        int eo = i / 896, r = i % 896, ei = r / 7, k = r % 7;
        g_watlas_t[(ei * 7 + k) * 128 + eo] = w_atlas[i];
    }
    if (i < 128 * 128) {
        int o = i / 128, e = i % 128;
        g_wk_t[e * 128 + o] = w_k[i];
    }
}

// ---------------- K1: conv1 over E + SiLU -> h1T (R3 exact) ------------------
__global__ void __launch_bounds__(128, 5)
conv1_kernel(const float* __restrict__ x, const float* __restrict__ b_emb) {
    __shared__ float xs[56 * XS_W];
    int t = threadIdx.x;
    int b = blockIdx.x;

    const float* xb = x + (size_t)b * 56 * 128;
    for (int i = t; i < 56 * 128; i += 128) {
        int a = i >> 7, e = i & 127;
        xs[a * XS_W + 3 + e] = xb[i];
    }
    if (t < 56) {
        float* row = xs + t * XS_W;
        row[0] = 0.f; row[1] = 0.f; row[2] = 0.f;
        row[131] = 0.f; row[132] = 0.f; row[133] = 0.f; row[134] = 0.f; row[135] = 0.f;
    }
    __syncthreads();

    int ep = t & 63, ah = t >> 6;
    int e0 = 2 * ep, aoff = 28 * ah;

    unsigned long long acc0[14], acc1[14];
#pragma unroll
    for (int j = 0; j < 14; j++) { acc0[j] = 0ULL; acc1[j] = 0ULL; }

    for (int ai = 0; ai < 56; ai++) {
        const float* xr = xs + ai * XS_W + e0;
        float xv[8];
#pragma unroll
        for (int j = 0; j < 8; j++) xv[j] = xr[j];
#pragma unroll
        for (int k = 0; k < 7; k++) {
            unsigned long long xb0 = bc2(xv[k]);
            unsigned long long xb1 = bc2(xv[k + 1]);
            const ulonglong2* wr = reinterpret_cast<const ulonglong2*>(
                g_wemb_t + (ai * 7 + k) * 56 + aoff);
#pragma unroll
            for (int p = 0; p < 7; p++) {
                ulonglong2 w = wr[p];
                fma2(acc0[2 * p],     w.x, xb0);
                fma2(acc0[2 * p + 1], w.y, xb0);
                fma2(acc1[2 * p],     w.x, xb1);
                fma2(acc1[2 * p + 1], w.y, xb1);
            }
        }
    }

#pragma unroll
    for (int v = 0; v < 2; v++) {
        float* dst = g_h1 + ((size_t)b * 128 + e0 + v) * 64;
        if (ah == 0) { dst[0] = 0.f; dst[1] = 0.f; dst[2] = 0.f; }
        else { dst[59] = 0.f; dst[60] = 0.f; dst[61] = 0.f; dst[62] = 0.f; dst[63] = 0.f; }
        const unsigned long long* av = v ? acc1 : acc0;
        int base = 3 + aoff;
#pragma unroll
        for (int j = 0; j < 14; j++) {
            float2 f = unpk(av[j]);
            dst[base + 2 * j]     = silu_f(f.x + b_emb[aoff + 2 * j]);
            dst[base + 2 * j + 1] = silu_f(f.y + b_emb[aoff + 2 * j + 1]);
        }
    }
}

// ---------------- K2: conv2 over A + SiLU + mean -> q (R3 exact) -------------
__global__ void __launch_bounds__(224, 3)
conv2_kernel(const float* __restrict__ b_atlas) {
    __shared__ __align__(16) float h1s[128 * 64];
    __shared__ float qsum[128];
    int tid = threadIdx.x;
    int b = blockIdx.x;

    const float4* src = reinterpret_cast<const float4*>(g_h1 + (size_t)b * 8192);
    float4* dst4 = reinterpret_cast<float4*>(h1s);
    for (int i = tid; i < 2048; i += 224) dst4[i] = src[i];
    if (tid < 128) qsum[tid] = 0.f;
    __syncthreads();

    int tx = tid % 14, g = tid / 14;
    int a0 = 4 * tx, eo0 = 8 * g;

    unsigned long long acc[4][4];
#pragma unroll
    for (int a = 0; a < 4; a++)
#pragma unroll
        for (int p = 0; p < 4; p++) acc[a][p] = 0ULL;

    for (int ei = 0; ei < 128; ei++) {
        const float* hr = h1s + ei * 64 + a0;
        float xv[10];
#pragma unroll
        for (int j = 0; j < 10; j++) xv[j] = hr[j];
#pragma unroll
        for (int k = 0; k < 7; k++) {
            const ulonglong2* wr = reinterpret_cast<const ulonglong2*>(
                g_watlas_t + (ei * 7 + k) * 128 + eo0);
            ulonglong2 wA = wr[0];
            ulonglong2 wB = wr[1];
#pragma unroll
            for (int a = 0; a < 4; a++) {
                unsigned long long xb = bc2(xv[k + a]);
                fma2(acc[a][0], wA.x, xb);
                fma2(acc[a][1], wA.y, xb);
                fma2(acc[a][2], wB.x, xb);
                fma2(acc[a][3], wB.y, xb);
            }
        }
    }

    float s[8];
#pragma unroll
    for (int j = 0; j < 8; j++) s[j] = 0.f;
#pragma unroll
    for (int a = 0; a < 4; a++)
#pragma unroll
        for (int p = 0; p < 4; p++) {
            float2 f = unpk(acc[a][p]);
            s[2 * p]     += silu_f(f.x + b_atlas[eo0 + 2 * p]);
            s[2 * p + 1] += silu_f(f.y + b_atlas[eo0 + 2 * p + 1]);
        }
#pragma unroll
    for (int j = 0; j < 8; j++) atomicAdd(&qsum[eo0 + j], s[j]);
    __syncthreads();
    if (tid < 128) g_q[b * 128 + tid] = qsum[tid] * (1.0f / 56.0f);
}

// ---------------- K3: k-proj (o-quad x 14l tiles) + LN + attention -----------
// 1 batch per 128-thread CTA. ks transposed [o][l], pitch 57.
__global__ void __launch_bounds__(128, 3)
attn_kernel(const float* __restrict__ x,
            const float* __restrict__ qn_w, const float* __restrict__ qn_b,
            const float* __restrict__ kn_w, const float* __restrict__ kn_b,
            const float* __restrict__ lq1, const float* __restrict__ lk1,
            const float* __restrict__ lq2, const float* __restrict__ lk2,
            float* __restrict__ out) {
    extern __shared__ __align__(16) float sm[];
    int t = threadIdx.x;
    int b = blockIdx.x;

    float* xsT = sm;            // [e][l] (128*56)
    float* ks  = sm + 7168;     // [o][l] pitch 57 (128*57)
    float* qv  = sm + 14464;    // 128
    float* sc  = sm + 14592;    // [h2][l] 8*56
    float* dd  = sm + 15040;    // [hp][l] 4*56
    float* lam = sm + 15264;

    const float* xb = x + (size_t)b * 7168;
    for (int i = t; i < 7168; i += 128) {
        int l = i >> 7, e = i & 127;
        xsT[e * 56 + l] = xb[i];
    }
    qv[t] = g_q[b * 128 + t];
    if (t == 0) {
        float s1 = 0.f, s2 = 0.f;
#pragma unroll
        for (int d = 0; d < 16; d++) { s1 += lq1[d] * lk1[d]; s2 += lq2[d] * lk2[d]; }
        lam[0] = __expf(s1) - __expf(s2) + 0.7f;
    }
    __syncthreads();

    // k projection: thread owns o-quad (oq = t&31) x 14 l's (lh = t>>5).
    // Per e: 7 LDS.64 x (warp-broadcast) + 1 LDG.128 wk + 28 fma2.
    {
        int oq = t & 31, lh = t >> 5;
        int o0 = 4 * oq, l0 = 14 * lh;
        unsigned long long acc[4][7];
#pragma unroll
        for (int o = 0; o < 4; o++)
#pragma unroll
            for (int j = 0; j < 7; j++) acc[o][j] = 0ULL;

        for (int e = 0; e < 128; e++) {
            float4 wq = *reinterpret_cast<const float4*>(g_wk_t + e * 128 + o0);
            const unsigned long long* xr =
                reinterpret_cast<const unsigned long long*>(xsT + e * 56 + l0);
            unsigned long long xv[7];
#pragma unroll
            for (int j = 0; j < 7; j++) xv[j] = xr[j];
            unsigned long long w0 = bc2(wq.x), w1 = bc2(wq.y);
            unsigned long long w2 = bc2(wq.z), w3 = bc2(wq.w);
#pragma unroll
            for (int j = 0; j < 7; j++) {
                fma2(acc[0][j], xv[j], w0);
                fma2(acc[1][j], xv[j], w1);
                fma2(acc[2][j], xv[j], w2);
                fma2(acc[3][j], xv[j], w3);
            }
        }
#pragma unroll
        for (int o = 0; o < 4; o++) {
            float* kr = ks + (o0 + o) * 57 + l0;
#pragma unroll
            for (int j = 0; j < 7; j++) {
                float2 f = unpk(acc[o][j]);
                kr[2 * j]     = f.x;
                kr[2 * j + 1] = f.y;
            }
        }
    }
    __syncthreads();

    // LayerNorm k: group (h, l) over 16 o-rows
    for (int gI = t; gI < 448; gI += 128) {
        int h = gI / 56, l = gI - h * 56;
        int ob = h * 16;
        float m = 0.f;
#pragma unroll
        for (int d = 0; d < 16; d++) m += ks[(ob + d) * 57 + l];
        m *= (1.0f / 16.0f);
        float var = 0.f;
#pragma unroll
        for (int d = 0; d < 16; d++) {
            float dv = ks[(ob + d) * 57 + l] - m;
            var += dv * dv;
        }
        var *= (1.0f / 16.0f);
        float rs = rsqrtf(var + 1e-5f);
#pragma unroll
        for (int d = 0; d < 16; d++) {
            float* p = ks + (ob + d) * 57 + l;
            *p = (*p - m) * rs * kn_w[d] + kn_b[d];
        }
    }
    if (t < 8) {
        float* qp = qv + t * 16;
        float m = 0.f;
#pragma unroll
        for (int d = 0; d < 16; d++) m += qp[d];
        m *= (1.0f / 16.0f);
        float var = 0.f;
#pragma unroll
        for (int d = 0; d < 16; d++) { float dv = qp[d] - m; var += dv * dv; }
        var *= (1.0f / 16.0f);
        float rs = rsqrtf(var + 1e-5f);
#pragma unroll
        for (int d = 0; d < 16; d++)
            qp[d] = ((qp[d] - m) * rs * qn_w[d] + qn_b[d]) * 0.25f;  // * HD^-0.5
    }
    __syncthreads();

    // attention scores
    for (int gI = t; gI < 448; gI += 128) {
        int h = gI / 56, l = gI - h * 56;
        int ob = h * 16;
        const float* qp = qv + h * 16;
        float s = 0.f;
#pragma unroll
        for (int d = 0; d < 16; d++) s += qp[d] * ks[(ob + d) * 57 + l];
        sc[h * 56 + l] = s;
    }
    __syncthreads();

    // softmax per head
    if (t < 8) {
        float* r = sc + t * 56;
        float mx = -1e30f;
        for (int l = 0; l < 56; l++) mx = fmaxf(mx, r[l]);
        float sum = 0.f;
        for (int l = 0; l < 56; l++) { float e = __expf(r[l] - mx); r[l] = e; sum += e; }
        float inv = 1.0f / sum;
        for (int l = 0; l < 56; l++) r[l] *= inv;
    }
    __syncthreads();

    // diff + softmax per head pair
    if (t < 4) {
        float lamv = lam[0];
        const float* p0 = sc + (2 * t) * 56;
        const float* p1 = sc + (2 * t + 1) * 56;
        float* dr = dd + t * 56;
        float mx = -1e30f;
        for (int l = 0; l < 56; l++) {
            float d = p0[l] - lamv * p1[l];
            dr[l] = d;
            mx = fmaxf(mx, d);
        }
        float sum = 0.f;
        for (int l = 0; l < 56; l++) { float e = __expf(dr[l] - mx); dr[l] = e; sum += e; }
        float inv = 1.0f / sum;
        for (int l = 0; l < 56; l++) dr[l] *= inv;
    }
    __syncthreads();

    if (t < 56) {
        out[(size_t)b * 56 + t] =
            0.25f * (dd[t] + dd[56 + t] + dd[112 + t] + dd[168 + t]);
    }
}

// ---------------- launch -----------------------------------------------------
extern "C" void kernel_launch(void* const* d_in, const int* in_sizes, int n_in,
                              void* d_out, int out_size) {
    const float* x       = (const float*)d_in[0];
    const float* w_emb   = (const float*)d_in[1];
    const float* b_emb   = (const float*)d_in[2];
    const float* w_atlas = (const float*)d_in[3];
    const float* b_atlas = (const float*)d_in[4];
    const float* w_k     = (const float*)d_in[5];
    const float* qn_w    = (const float*)d_in[6];
    const float* qn_b    = (const float*)d_in[7];
    const float* kn_w    = (const float*)d_in[8];
    const float* kn_b    = (const float*)d_in[9];
    const float* lq1     = (const float*)d_in[10];
    const float* lk1     = (const float*)d_in[11];
    const float* lq2     = (const float*)d_in[12];
    const float* lk2     = (const float*)d_in[13];
    float* out = (float*)d_out;

    const int SMEM3 = 15268 * (int)sizeof(float);   // 61,072 B
    cudaFuncSetAttribute((const void*)attn_kernel,
                         cudaFuncAttributeMaxDynamicSharedMemorySize, SMEM3);

    repack_kernel<<<448, 256>>>(w_emb, w_atlas, w_k);
    conv1_kernel<<<NB, 128>>>(x, b_emb);
    conv2_kernel<<<NB, 224>>>(b_atlas);
    attn_kernel<<<NB, 128, SMEM3>>>(x, qn_w, qn_b, kn_w, kn_b,
                                    lq1, lk1, lq2, lk2, out);
    (void)in_sizes; (void)n_in; (void)out_size;
}

// round 13
// speedup vs baseline: 1.2955x; 1.0181x over previous
#include <cuda_runtime.h>
#include <cstdint>
#include <cstddef>

#define NB   8192
#define XS_W 136   // conv1 smem row width (halo 3+5, padded)

// ---------------- scratch (device globals) ----------------------------------
__device__ __align__(16) float g_wemb_t[56 * 7 * 56];       // [a_in][k][a_out]
__device__ __align__(16) float g_watlas_t[128 * 7 * 128];   // [e_in][k][e_out]
__device__ __align__(16) float g_wk_t[128 * 128];           // [e][o]
__device__ __align__(16) float g_h1[(size_t)NB * 128 * 64]; // [b][e][a+3], halo 0
__device__ __align__(16) float g_q[NB * 128];               // q pre-LN

// ---------------- f32x2 helpers ---------------------------------------------
__device__ __forceinline__ void fma2(unsigned long long &d,
                                     unsigned long long a,
                                     unsigned long long b) {
    asm("fma.rn.f32x2 %0, %1, %2, %3;" : "=l"(d) : "l"(a), "l"(b), "l"(d));
}
__device__ __forceinline__ unsigned long long bc2(float x) {
    unsigned int xi = __float_as_uint(x);
    unsigned long long r;
    asm("mov.b64 %0, {%1, %2};" : "=l"(r) : "r"(xi), "r"(xi));
    return r;
}
__device__ __forceinline__ float2 unpk(unsigned long long v) {
    unsigned int lo, hi;
    asm("mov.b64 {%0, %1}, %2;" : "=r"(lo), "=r"(hi) : "l"(v));
    float2 f; f.x = __uint_as_float(lo); f.y = __uint_as_float(hi);
    return f;
}
__device__ __forceinline__ float silu_f(float v) {
    return v / (1.0f + __expf(-v));
}

// ---------------- K0: repack weights ----------------------------------------
__global__ void repack_kernel(const float* __restrict__ w_emb,
                              const float* __restrict__ w_atlas,
                              const float* __restrict__ w_k) {
    int i = blockIdx.x * 256 + threadIdx.x;
    if (i < 56 * 56 * 7) {
        int ao = i / 392, r = i % 392, ai = r / 7, k = r % 7;
        g_wemb_t[(ai * 7 + k) * 56 + ao] = w_emb[i];
    }
    if (i < 128 * 128 * 7) {
        int eo = i / 896, r = i % 896, ei = r / 7, k = r % 7;
        g_watlas_t[(ei * 7 + k) * 128 + eo] = w_atlas[i];
    }
    if (i < 128 * 128) {
        int o = i / 128, e = i % 128;
        g_wk_t[e * 128 + o] = w_k[i];
    }
}

// ---------------- K1: conv1 over E + SiLU -> h1T -----------------------------
// 1 batch per 128-thread CTA; bc2 hoisted (8 distinct broadcasts per ai).
__global__ void __launch_bounds__(128, 5)
conv1_kernel(const float* __restrict__ x, const float* __restrict__ b_emb) {
    __shared__ float xs[56 * XS_W];
    int t = threadIdx.x;
    int b = blockIdx.x;

    const float* xb = x + (size_t)b * 56 * 128;
    for (int i = t; i < 56 * 128; i += 128) {
        int a = i >> 7, e = i & 127;
        xs[a * XS_W + 3 + e] = xb[i];
    }
    if (t < 56) {
        float* row = xs + t * XS_W;
        row[0] = 0.f; row[1] = 0.f; row[2] = 0.f;
        row[131] = 0.f; row[132] = 0.f; row[133] = 0.f; row[134] = 0.f; row[135] = 0.f;
    }
    __syncthreads();

    int ep = t & 63, ah = t >> 6;
    int e0 = 2 * ep, aoff = 28 * ah;

    unsigned long long acc0[14], acc1[14];
#pragma unroll
    for (int j = 0; j < 14; j++) { acc0[j] = 0ULL; acc1[j] = 0ULL; }

    for (int ai = 0; ai < 56; ai++) {
        const float* xr = xs + ai * XS_W + e0;
        unsigned long long xbc[8];
#pragma unroll
        for (int j = 0; j < 8; j++) xbc[j] = bc2(xr[j]);
#pragma unroll
        for (int k = 0; k < 7; k++) {
            unsigned long long xb0 = xbc[k];
            unsigned long long xb1 = xbc[k + 1];
            const ulonglong2* wr = reinterpret_cast<const ulonglong2*>(
                g_wemb_t + (ai * 7 + k) * 56 + aoff);
#pragma unroll
            for (int p = 0; p < 7; p++) {
                ulonglong2 w = wr[p];
                fma2(acc0[2 * p],     w.x, xb0);
                fma2(acc0[2 * p + 1], w.y, xb0);
                fma2(acc1[2 * p],     w.x, xb1);
                fma2(acc1[2 * p + 1], w.y, xb1);
            }
        }
    }

#pragma unroll
    for (int v = 0; v < 2; v++) {
        float* dst = g_h1 + ((size_t)b * 128 + e0 + v) * 64;
        if (ah == 0) { dst[0] = 0.f; dst[1] = 0.f; dst[2] = 0.f; }
        else { dst[59] = 0.f; dst[60] = 0.f; dst[61] = 0.f; dst[62] = 0.f; dst[63] = 0.f; }
        const unsigned long long* av = v ? acc1 : acc0;
        int base = 3 + aoff;
#pragma unroll
        for (int j = 0; j < 14; j++) {
            float2 f = unpk(av[j]);
            dst[base + 2 * j]     = silu_f(f.x + b_emb[aoff + 2 * j]);
            dst[base + 2 * j + 1] = silu_f(f.y + b_emb[aoff + 2 * j + 1]);
        }
    }
}

// ---------------- K2: conv2 over A + SiLU + mean -> q ------------------------
// 1 batch per 224-thread CTA: tx=a-quad (14), g=eo-octet (16).
// bc2 hoisted: 10 distinct broadcasts per ei (j = k + a).
__global__ void __launch_bounds__(224, 4)
conv2_kernel(const float* __restrict__ b_atlas) {
    __shared__ __align__(16) float h1s[128 * 64];
    __shared__ float qsum[128];
    int tid = threadIdx.x;
    int b = blockIdx.x;

    const float4* src = reinterpret_cast<const float4*>(g_h1 + (size_t)b * 8192);
    float4* dst4 = reinterpret_cast<float4*>(h1s);
    for (int i = tid; i < 2048; i += 224) dst4[i] = src[i];
    if (tid < 128) qsum[tid] = 0.f;
    __syncthreads();

    int tx = tid % 14, g = tid / 14;
    int a0 = 4 * tx, eo0 = 8 * g;

    unsigned long long acc[4][4];
#pragma unroll
    for (int a = 0; a < 4; a++)
#pragma unroll
        for (int p = 0; p < 4; p++) acc[a][p] = 0ULL;

    // weight base in ulonglong2 units: (ei*7+k)*128 + eo0 floats
    const ulonglong2* wbase =
        reinterpret_cast<const ulonglong2*>(g_watlas_t) + (eo0 >> 2);

    for (int ei = 0; ei < 128; ei++) {
        const float* hr = h1s + ei * 64 + a0;
        float4 v0 = *reinterpret_cast<const float4*>(hr);
        float4 v1 = *reinterpret_cast<const float4*>(hr + 4);
        float2 v2 = *reinterpret_cast<const float2*>(hr + 8);
        unsigned long long xbc[10];
        xbc[0] = bc2(v0.x); xbc[1] = bc2(v0.y); xbc[2] = bc2(v0.z); xbc[3] = bc2(v0.w);
        xbc[4] = bc2(v1.x); xbc[5] = bc2(v1.y); xbc[6] = bc2(v1.z); xbc[7] = bc2(v1.w);
        xbc[8] = bc2(v2.x); xbc[9] = bc2(v2.y);

        const ulonglong2* wr = wbase + ei * 224;
#pragma unroll
        for (int k = 0; k < 7; k++) {
            ulonglong2 wA = wr[k * 32];
            ulonglong2 wB = wr[k * 32 + 1];
#pragma unroll
            for (int a = 0; a < 4; a++) {
                unsigned long long xv = xbc[k + a];
                fma2(acc[a][0], wA.x, xv);
                fma2(acc[a][1], wA.y, xv);
                fma2(acc[a][2], wB.x, xv);
                fma2(acc[a][3], wB.y, xv);
            }
        }
    }

    float s[8];
#pragma unroll
    for (int j = 0; j < 8; j++) s[j] = 0.f;
#pragma unroll
    for (int a = 0; a < 4; a++)
#pragma unroll
        for (int p = 0; p < 4; p++) {
            float2 f = unpk(acc[a][p]);
            s[2 * p]     += silu_f(f.x + b_atlas[eo0 + 2 * p]);
            s[2 * p + 1] += silu_f(f.y + b_atlas[eo0 + 2 * p + 1]);
        }
#pragma unroll
    for (int j = 0; j < 8; j++) atomicAdd(&qsum[eo0 + j], s[j]);
    __syncthreads();
    if (tid < 128) g_q[b * 128 + tid] = qsum[tid] * (1.0f / 56.0f);
}

// ---------------- K3: k-proj (o-quad x 14l tiles) + LN + attention -----------
// 1 batch per 128-thread CTA. ks transposed [o][l], pitch 57. (R11 exact)
__global__ void __launch_bounds__(128, 3)
attn_kernel(const float* __restrict__ x,
            const float* __restrict__ qn_w, const float* __restrict__ qn_b,
            const float* __restrict__ kn_w, const float* __restrict__ kn_b,
            const float* __restrict__ lq1, const float* __restrict__ lk1,
            const float* __restrict__ lq2, const float* __restrict__ lk2,
            float* __restrict__ out) {
    extern __shared__ __align__(16) float sm[];
    int t = threadIdx.x;
    int b = blockIdx.x;

    float* xsT = sm;            // [e][l] (128*56)
    float* ks  = sm + 7168;     // [o][l] pitch 57 (128*57)
    float* qv  = sm + 14464;    // 128
    float* sc  = sm + 14592;    // [h2][l] 8*56
    float* dd  = sm + 15040;    // [hp][l] 4*56
    float* lam = sm + 15264;

    const float* xb = x + (size_t)b * 7168;
    for (int i = t; i < 7168; i += 128) {
        int l = i >> 7, e = i & 127;
        xsT[e * 56 + l] = xb[i];
    }
    qv[t] = g_q[b * 128 + t];
    if (t == 0) {
        float s1 = 0.f, s2 = 0.f;
#pragma unroll
        for (int d = 0; d < 16; d++) { s1 += lq1[d] * lk1[d]; s2 += lq2[d] * lk2[d]; }
        lam[0] = __expf(s1) - __expf(s2) + 0.7f;
    }
    __syncthreads();

    {
        int oq = t & 31, lh = t >> 5;
        int o0 = 4 * oq, l0 = 14 * lh;
        unsigned long long acc[4][7];
#pragma unroll
        for (int o = 0; o < 4; o++)
#pragma unroll
            for (int j = 0; j < 7; j++) acc[o][j] = 0ULL;

        for (int e = 0; e < 128; e++) {
            float4 wq = *reinterpret_cast<const float4*>(g_wk_t + e * 128 + o0);
            const unsigned long long* xr =
                reinterpret_cast<const unsigned long long*>(xsT + e * 56 + l0);
            unsigned long long xv[7];
#pragma unroll
            for (int j = 0; j < 7; j++) xv[j] = xr[j];
            unsigned long long w0 = bc2(wq.x), w1 = bc2(wq.y);
            unsigned long long w2 = bc2(wq.z), w3 = bc2(wq.w);
#pragma unroll
            for (int j = 0; j < 7; j++) {
                fma2(acc[0][j], xv[j], w0);
                fma2(acc[1][j], xv[j], w1);
                fma2(acc[2][j], xv[j], w2);
                fma2(acc[3][j], xv[j], w3);
            }
        }
#pragma unroll
        for (int o = 0; o < 4; o++) {
            float* kr = ks + (o0 + o) * 57 + l0;
#pragma unroll
            for (int j = 0; j < 7; j++) {
                float2 f = unpk(acc[o][j]);
                kr[2 * j]     = f.x;
                kr[2 * j + 1] = f.y;
            }
        }
    }
    __syncthreads();

    for (int gI = t; gI < 448; gI += 128) {
        int h = gI / 56, l = gI - h * 56;
        int ob = h * 16;
        float m = 0.f;
#pragma unroll
        for (int d = 0; d < 16; d++) m += ks[(ob + d) * 57 + l];
        m *= (1.0f / 16.0f);
        float var = 0.f;
#pragma unroll
        for (int d = 0; d < 16; d++) {
            float dv = ks[(ob + d) * 57 + l] - m;
            var += dv * dv;
        }
        var *= (1.0f / 16.0f);
        float rs = rsqrtf(var + 1e-5f);
#pragma unroll
        for (int d = 0; d < 16; d++) {
            float* p = ks + (ob + d) * 57 + l;
            *p = (*p - m) * rs * kn_w[d] + kn_b[d];
        }
    }
    if (t < 8) {
        float* qp = qv + t * 16;
        float m = 0.f;
#pragma unroll
        for (int d = 0; d < 16; d++) m += qp[d];
        m *= (1.0f / 16.0f);
        float var = 0.f;
#pragma unroll
        for (int d = 0; d < 16; d++) { float dv = qp[d] - m; var += dv * dv; }
        var *= (1.0f / 16.0f);
        float rs = rsqrtf(var + 1e-5f);
#pragma unroll
        for (int d = 0; d < 16; d++)
            qp[d] = ((qp[d] - m) * rs * qn_w[d] + qn_b[d]) * 0.25f;  // * HD^-0.5
    }
    __syncthreads();

    for (int gI = t; gI < 448; gI += 128) {
        int h = gI / 56, l = gI - h * 56;
        int ob = h * 16;
        const float* qp = qv + h * 16;
        float s = 0.f;
#pragma unroll
        for (int d = 0; d < 16; d++) s += qp[d] * ks[(ob + d) * 57 + l];
        sc[h * 56 + l] = s;
    }
    __syncthreads();

    if (t < 8) {
        float* r = sc + t * 56;
        float mx = -1e30f;
        for (int l = 0; l < 56; l++) mx = fmaxf(mx, r[l]);
        float sum = 0.f;
        for (int l = 0; l < 56; l++) { float e = __expf(r[l] - mx); r[l] = e; sum += e; }
        float inv = 1.0f / sum;
        for (int l = 0; l < 56; l++) r[l] *= inv;
    }
    __syncthreads();

    if (t < 4) {
        float lamv = lam[0];
        const float* p0 = sc + (2 * t) * 56;
        const float* p1 = sc + (2 * t + 1) * 56;
        float* dr = dd + t * 56;
        float mx = -1e30f;
        for (int l = 0; l < 56; l++) {
            float d = p0[l] - lamv * p1[l];
            dr[l] = d;
            mx = fmaxf(mx, d);
        }
        float sum = 0.f;
        for (int l = 0; l < 56; l++) { float e = __expf(dr[l] - mx); dr[l] = e; sum += e; }
        float inv = 1.0f / sum;
        for (int l = 0; l < 56; l++) dr[l] *= inv;
    }
    __syncthreads();

    if (t < 56) {
        out[(size_t)b * 56 + t] =
            0.25f * (dd[t] + dd[56 + t] + dd[112 + t] + dd[168 + t]);
    }
}

// ---------------- launch -----------------------------------------------------
extern "C" void kernel_launch(void* const* d_in, const int* in_sizes, int n_in,
                              void* d_out, int out_size) {
    const float* x       = (const float*)d_in[0];
    const float* w_emb   = (const float*)d_in[1];
    const float* b_emb   = (const float*)d_in[2];
    const float* w_atlas = (const float*)d_in[3];
    const float* b_atlas = (const float*)d_in[4];
    const float* w_k     = (const float*)d_in[5];
    const float* qn_w    = (const float*)d_in[6];
    const float* qn_b    = (const float*)d_in[7];
    const float* kn_w    = (const float*)d_in[8];
    const float* kn_b    = (const float*)d_in[9];
    const float* lq1     = (const float*)d_in[10];
    const float* lk1     = (const float*)d_in[11];
    const float* lq2     = (const float*)d_in[12];
    const float* lk2     = (const float*)d_in[13];
    float* out = (float*)d_out;

    const int SMEM3 = 15268 * (int)sizeof(float);   // 61,072 B
    cudaFuncSetAttribute((const void*)attn_kernel,
                         cudaFuncAttributeMaxDynamicSharedMemorySize, SMEM3);

    repack_kernel<<<448, 256>>>(w_emb, w_atlas, w_k);
    conv1_kernel<<<NB, 128>>>(x, b_emb);
    conv2_kernel<<<NB, 224>>>(b_atlas);
    attn_kernel<<<NB, 128, SMEM3>>>(x, qn_w, qn_b, kn_w, kn_b,
                                    lq1, lk1, lq2, lk2, out);
    (void)in_sizes; (void)n_in; (void)out_size;
}